// round 13
// baseline (speedup 1.0000x reference)
#include <cuda.h>
#include <cuda_runtime.h>
#include <cuda_fp16.h>
#include <cstdint>

#define HEADS 8
#define NBAT  8
#define NTOK  1024
#define NL    3
#define CH    256
#define RTOT  (NBAT*NTOK*NL)   // 24576 rows per stream

// ---------------- scratch (device globals: allocation-free) ----------------
// v pair-interleaved per (s,b,h): [m/2=512][104 u32] (cols 0..95 data, pad)
__device__ __align__(256) __half g_vph[2u*64u*512u*104u*2u];
// attout fp16: [s][(b,n)][l*256 + h*32 + c]  (768 per row; (b,n,l) rows contiguous 256)
__device__ __align__(256) __half g_aoh[2u*NBAT*NTOK*NL*CH];
// weights fp16 row-major [j][256]: rows 0..255 = Wv, 256..511 = Wo
__device__ __align__(256) __half g_Wh[2*CH*CH];

// ---------------- helpers ----------------
__device__ __forceinline__ void mma16(float* d, const uint32_t* a, const uint32_t* b) {
    asm("mma.sync.aligned.m16n8k16.row.col.f32.f16.f16.f32 "
        "{%0,%1,%2,%3}, {%4,%5,%6,%7}, {%8,%9}, {%0,%1,%2,%3};"
        : "+f"(d[0]), "+f"(d[1]), "+f"(d[2]), "+f"(d[3])
        : "r"(a[0]), "r"(a[1]), "r"(a[2]), "r"(a[3]), "r"(b[0]), "r"(b[1]));
}
__device__ __forceinline__ uint32_t pack2(float lo, float hi) {
    uint32_t r; asm("cvt.rn.f16x2.f32 %0, %1, %2;" : "=r"(r) : "f"(hi), "f"(lo)); return r;
}
__device__ __forceinline__ uint32_t elect1() {
    uint32_t p;
    asm volatile("{\n\t.reg .pred p;\n\telect.sync _|p, 0xFFFFFFFF;\n\t"
                 "selp.b32 %0, 1, 0, p;\n\t}" : "=r"(p));
    return p;
}
__device__ __forceinline__ void bulk_g2s(uint32_t dst, const void* src,
                                         uint32_t bytes, uint32_t mbar) {
    asm volatile("cp.async.bulk.shared::cta.global.mbarrier::complete_tx::bytes "
                 "[%0], [%1], %2, [%3];"
                 :: "r"(dst), "l"(src), "r"(bytes), "r"(mbar) : "memory");
}
__device__ __forceinline__ void tma2d(uint32_t dst, const CUtensorMap* tm,
                                      int x, int y, uint32_t mbar) {
    asm volatile(
        "cp.async.bulk.tensor.2d.shared::cta.global.tile.mbarrier::complete_tx::bytes "
        "[%0], [%1, {%2, %3}], [%4];"
        :: "r"(dst), "l"(tm), "r"(x), "r"(y), "r"(mbar) : "memory");
}
__device__ __forceinline__ void tma3d(uint32_t dst, const CUtensorMap* tm,
                                      int x, int y, int z, uint32_t mbar) {
    asm volatile(
        "cp.async.bulk.tensor.3d.shared::cta.global.tile.mbarrier::complete_tx::bytes "
        "[%0], [%1, {%2, %3, %4}], [%5];"
        :: "r"(dst), "l"(tm), "r"(x), "r"(y), "r"(z), "r"(mbar) : "memory");
}
#define MBAR_INIT(a, c) \
    asm volatile("mbarrier.init.shared.b64 [%0], %1;" :: "r"((uint32_t)(a)), "r"((uint32_t)(c)) : "memory")
#define MBAR_EXPECT(a, b) \
    asm volatile("mbarrier.arrive.expect_tx.shared.b64 _, [%0], %1;" :: "r"((uint32_t)(a)), "r"((uint32_t)(b)) : "memory")
#define MBAR_ARRIVE(a) \
    asm volatile("mbarrier.arrive.shared.b64 _, [%0];" :: "r"((uint32_t)(a)) : "memory")
#define MBAR_WAIT(mb, ph) do { \
    uint32_t _m = (uint32_t)(mb), _p = (uint32_t)(ph), _d; \
    asm volatile("{\n\t.reg .pred p;\n\t" \
        "mbarrier.try_wait.parity.acquire.cta.shared::cta.b64 p, [%1], %2;\n\t" \
        "selp.b32 %0, 1, 0, p;\n\t}" : "=r"(_d) : "r"(_m), "r"(_p) : "memory"); \
    if (!_d) { \
        asm volatile("{\n\t.reg .pred P1;\n\t" \
            "WL_%=:\n\t" \
            "mbarrier.try_wait.parity.acquire.cta.shared::cta.b64 P1, [%0], %1, 0x989680;\n\t" \
            "@P1 bra.uni WD_%=;\n\tbra.uni WL_%=;\n\tWD_%=:\n\t}" \
            :: "r"(_m), "r"(_p) : "memory"); \
    } \
} while(0)

// =====================================================================
// W prep: fp16 weights
// =====================================================================
__global__ void wprep_kernel(const float* __restrict__ Wv, const float* __restrict__ Wo) {
    int i = blockIdx.x * 256 + threadIdx.x;
    g_Wh[i]         = __float2half_rn(Wv[i]);
    g_Wh[CH*CH + i] = __float2half_rn(Wo[i]);
}

// =====================================================================
// proj (TMA + sync-free mbarrier pipeline, 8 warps 4x2, tile 128x64):
//  MODE 0: A=equ f32 via 3D TMA (rows (b,l,m)), 8 ksteps BK=32, 4 stages
//          -> smem transpose -> coalesced u32 pair store into g_vph
//  MODE 1: A=g_aoh fp16 via 2D TMA, 4 ksteps BK=64, 3 stages
//          -> out f32 + residual
//  W: full 64x256 fp16 tile preloaded once via 4 TMAs (own tx barrier).
// smem: hdr 1KB | W 32KB (4 quads of 64 rows x 128B SW128) | A stages 16KB
// =====================================================================
#define PW_OFF  1024
#define PA_OFF  (1024 + 32768)
#define P0_SMEM (PA_OFF + 4*16384)   // 98304
#define P1_SMEM (PA_OFF + 3*16384)   // 82944 -> 81920? (3*16384=49152; =82176) use exact below

template<int MODE>
__global__ void __launch_bounds__(256, 2) proj_kernel(
    const __grid_constant__ CUtensorMap tA1,
    const __grid_constant__ CUtensorMap tA2,
    const __grid_constant__ CUtensorMap tW,
    const float* __restrict__ equ1, const float* __restrict__ equ2,
    float* __restrict__ out)
{
    constexpr int KS = (MODE == 0) ? 8 : 4;    // ksteps
    constexpr int ST = (MODE == 0) ? 4 : 3;    // stages
    constexpr int KKN = (MODE == 0) ? 2 : 4;   // k16 per kstep

    extern __shared__ char psm[];
    char* hdr = (char*)(((uintptr_t)psm + 1023) & ~(uintptr_t)1023);
    const uint32_t hdr_s = (uint32_t)__cvta_generic_to_shared(hdr);
    char* Wp = hdr + PW_OFF;
    char* Ap = hdr + PA_OFF;
    const uint32_t W_s = hdr_s + PW_OFF;
    const uint32_t A_s = hdr_s + PA_OFF;

    const int s = blockIdx.z;
    const int tid = threadIdx.x;
    const int warp = tid >> 5, lane = tid & 31;
    const int wm = warp >> 1, wn = warp & 1;
    const int g = lane >> 2, tg = lane & 3;

    // tile decode
    int mt = 0, bb = 0, ll = 0, jt = 0, rbase = 0, jbase;
    if constexpr (MODE == 0) {
        mt = blockIdx.x;
        int yy = blockIdx.y;
        jt = yy & 3; ll = (yy >> 2) % 3; bb = yy / 12;
        jbase = jt * 64;
    } else {
        rbase = blockIdx.x * 128;
        jbase = blockIdx.y * 64;
    }
    const int wy = (MODE ? 256 : 0) + jbase;   // W row base in g_Wh

    if (tid == 0) {
        #pragma unroll
        for (int p = 0; p < ST; p++) {
            MBAR_INIT(hdr_s + p*8, 1);         // full (tx)
            MBAR_INIT(hdr_s + 64 + p*8, 8);    // empty (8 warps)
        }
        MBAR_INIT(hdr_s + 128, 1);             // W barrier (tx)
    }
    __syncthreads();

    auto issue_stage = [&](int ks, int st) {   // single elected thread
        MBAR_EXPECT(hdr_s + st*8, 16384);
        if constexpr (MODE == 0) {
            tma3d(A_s + st*16384, s ? &tA2 : &tA1,
                  ks*32, ll, bb*1024 + mt*128, hdr_s + st*8);
        } else {
            tma2d(A_s + st*16384, &tA1,
                  ks*64, s*RTOT + rbase, hdr_s + st*8);
        }
    };

    if (warp == 0 && elect1()) {
        MBAR_EXPECT(hdr_s + 128, 32768);
        #pragma unroll
        for (int q = 0; q < 4; q++)
            tma2d(W_s + q*8192, &tW, q*64, wy, hdr_s + 128);
        #pragma unroll
        for (int p = 0; p < ST; p++) issue_stage(p, p);
    }

    float acc[2][4][4];
    #pragma unroll
    for (int i = 0; i < 2; i++)
        #pragma unroll
        for (int j = 0; j < 4; j++)
            #pragma unroll
            for (int k = 0; k < 4; k++) acc[i][j][k] = 0.f;

    // per-thread SW128 XOR (row % 8 == g for all rows this thread touches)
    const uint32_t gx = (uint32_t)(g << 4);

    MBAR_WAIT(hdr_s + 128, 0);                 // W resident

    for (int ks = 0; ks < KS; ks++) {
        const int st = ks % ST;
        const int ph = (ks / ST) & 1;
        MBAR_WAIT(hdr_s + st*8, ph);

        const char* Ad = Ap + st * 16384;
        #pragma unroll
        for (int kk = 0; kk < KKN; kk++) {
            uint32_t a[2][4];
            #pragma unroll
            for (int mi = 0; mi < 2; mi++) {
                const int r = wm*32 + mi*16 + g;
                if constexpr (MODE == 0) {
                    // f32 rows of 128B: pairs at byte (2*tg*4 + kk*64? ) ->
                    // col f32 = kk*16 + 2*tg (+8); byte = col*4 ^ gx
                    const char* Ar = Ad + r * 128;
                    uint32_t c0 = (uint32_t)((kk*16 + 2*tg) * 4) ^ gx;
                    uint32_t c1 = (uint32_t)((kk*16 + 2*tg + 8) * 4) ^ gx;
                    float2 p0 = *(const float2*)(Ar + c0);
                    float2 p1 = *(const float2*)(Ar + 1024 + c0);
                    float2 p2 = *(const float2*)(Ar + c1);
                    float2 p3 = *(const float2*)(Ar + 1024 + c1);
                    a[mi][0] = pack2(p0.x, p0.y);
                    a[mi][1] = pack2(p1.x, p1.y);
                    a[mi][2] = pack2(p2.x, p2.y);
                    a[mi][3] = pack2(p3.x, p3.y);
                } else {
                    // fp16 rows of 128B (64 halves = 32 u32): col u32 = kk*8+tg (+4)
                    const char* Ar = Ad + r * 128;
                    uint32_t c0 = (uint32_t)((kk*8 + tg) * 4) ^ gx;
                    uint32_t c1 = (uint32_t)((kk*8 + tg + 4) * 4) ^ gx;
                    a[mi][0] = *(const uint32_t*)(Ar + c0);
                    a[mi][1] = *(const uint32_t*)(Ar + 1024 + c0);
                    a[mi][2] = *(const uint32_t*)(Ar + c1);
                    a[mi][3] = *(const uint32_t*)(Ar + 1024 + c1);
                }
            }
            // W quadrant/col for this (ks, kk): global u32 col = ks*(16 or 32) + kk*8 + tg
            const int q  = (MODE == 0) ? (ks >> 1) : ks;
            const int cb = (MODE == 0) ? ((ks & 1) * 16 + kk*8 + tg) : (kk*8 + tg);
            #pragma unroll
            for (int nj = 0; nj < 4; nj++) {
                const int j = wn*32 + nj*8 + g;
                const char* Wr = Wp + q*8192 + j*128;
                uint32_t b[2];
                b[0] = *(const uint32_t*)(Wr + (((uint32_t)(cb*4)) ^ gx));
                b[1] = *(const uint32_t*)(Wr + (((uint32_t)((cb+4)*4)) ^ gx));
                #pragma unroll
                for (int mi = 0; mi < 2; mi++) mma16(acc[mi][nj], a[mi], b);
            }
        }

        if (elect1()) MBAR_ARRIVE(hdr_s + 64 + st*8);
        if (warp == 0 && ks + ST < KS) {
            MBAR_WAIT(hdr_s + 64 + st*8, ph);
            if (elect1()) issue_stage(ks + ST, st);
        }
    }

    if constexpr (MODE == 0) {
        // transpose epilogue in smem (reuse W region after full sync)
        __syncthreads();
        __half* smh = (__half*)Wp;
        #pragma unroll
        for (int mi = 0; mi < 2; mi++)
            #pragma unroll
            for (int nj = 0; nj < 4; nj++) {
                const int jl = wn*32 + nj*8 + 2*tg;
                #pragma unroll
                for (int half = 0; half < 2; half++) {
                    const int ml = wm*32 + mi*16 + g + half*8;
                    smh[jl*138 + ml]     = __float2half_rn(acc[mi][nj][half*2]);
                    smh[(jl+1)*138 + ml] = __float2half_rn(acc[mi][nj][half*2+1]);
                }
            }
        __syncthreads();
        const uint32_t* smu = (const uint32_t*)Wp;
        uint32_t* vpu = (uint32_t*)g_vph;
        #pragma unroll
        for (int p = 0; p < 16; p++) {
            int idx = p*256 + tid;
            int j = idx & 63, mp = idx >> 6;
            uint32_t v = smu[j*69 + mp];
            int jg = jt*64 + j;
            int h = jg >> 5, c = jg & 31;
            int sbh = s*64 + bb*8 + h;
            vpu[((size_t)sbh*512 + mt*64 + mp)*104 + ll*32 + c] = v;
        }
    } else {
        #pragma unroll
        for (int mi = 0; mi < 2; mi++)
            #pragma unroll
            for (int nj = 0; nj < 4; nj++) {
                const int j = jbase + wn*32 + nj*8 + 2*tg;
                #pragma unroll
                for (int half = 0; half < 2; half++) {
                    const int r = rbase + wm*32 + mi*16 + g + half*8;
                    const float* R = s ? equ2 : equ1;
                    size_t o = (size_t)r*CH + j;
                    float2 rr = *(const float2*)&R[o];
                    float2 w = make_float2(acc[mi][nj][half*2] + rr.x,
                                           acc[mi][nj][half*2+1] + rr.y);
                    *(float2*)&out[(size_t)s*RTOT*CH + o] = w;
                }
            }
    }
}

// =====================================================================
// attn: unchanged from R10 (proven). per (s,bh,mt):
// aoh(128 x 96) = att(128x1024) @ v(1024x96), fp16 MMA, 12 warps 4x3.
// A: 2D TMA; B: one 6656B bulk; both on full[st]; sync-free pipeline.
// =====================================================================
#define AT_STGB 23552
#define AT_BOFF 16384
#define AT_TX   23040
#define ATTN_SMEM (2048 + 4*AT_STGB)

__global__ void __launch_bounds__(384, 2) attn_kernel(
    const __grid_constant__ CUtensorMap tmap)
{
    extern __shared__ char smraw[];
    char* hdr = (char*)(((uintptr_t)smraw + 1023) & ~(uintptr_t)1023);
    char* datap = hdr + 1024;
    const uint32_t hdr_s = (uint32_t)__cvta_generic_to_shared(hdr);
    const uint32_t data_s = hdr_s + 1024;

    const int mt = blockIdx.x, bh = blockIdx.y, s = blockIdx.z;
    const int sbh = s*64 + bh;
    const int rowbase = sbh*1024 + mt*128;
    const uint32_t* vp = (const uint32_t*)g_vph + (size_t)sbh * 512 * 104;

    const int tid = threadIdx.x;
    const int warp = tid >> 5, lane = tid & 31;
    const int wm = warp & 3, wn = warp >> 2;
    const int g = lane >> 2, tg = lane & 3;

    if (tid == 0) {
        #pragma unroll
        for (int p = 0; p < 4; p++) {
            MBAR_INIT(hdr_s + p*8, 1);
            MBAR_INIT(hdr_s + 64 + p*8, 12);
        }
    }
    __syncthreads();

    auto issue_stage = [&](int ks, int st) {
        const uint32_t sofs = st * AT_STGB;
        MBAR_EXPECT(hdr_s + st*8, AT_TX);
        tma2d(data_s + sofs, &tmap, ks*32, rowbase, hdr_s + st*8);
        bulk_g2s(data_s + sofs + AT_BOFF, vp + (size_t)ks*16*104, 6656,
                 hdr_s + st*8);
    };

    if (warp == 0 && elect1()) {
        #pragma unroll
        for (int p = 0; p < 4; p++) issue_stage(p, p);
    }

    uint32_t cx[2][2];
    #pragma unroll
    for (int kk = 0; kk < 2; kk++)
        #pragma unroll
        for (int ss = 0; ss < 2; ss++)
            cx[kk][ss] = (uint32_t)((kk*64 + tg*8 + ss*32) ^ (g << 4));

    float acc[2][4][4];
    #pragma unroll
    for (int i = 0; i < 2; i++)
        #pragma unroll
        for (int j = 0; j < 4; j++)
            #pragma unroll
            for (int k = 0; k < 4; k++) acc[i][j][k] = 0.f;

    for (int ks = 0; ks < 32; ks++) {
        const int st = ks & 3;
        const int ph = (ks >> 2) & 1;
        MBAR_WAIT(hdr_s + st*8, ph);

        const char* Ad = datap + st * AT_STGB;
        const uint32_t* Bd = (const uint32_t*)(Ad + AT_BOFF);
        #pragma unroll
        for (int kk = 0; kk < 2; kk++) {
            uint32_t a[2][4];
            #pragma unroll
            for (int mi = 0; mi < 2; mi++) {
                const char* Ar = Ad + (wm*32 + mi*16 + g) * 128;
                float2 p0 = *(const float2*)(Ar + cx[kk][0]);
                float2 p1 = *(const float2*)(Ar + 1024 + cx[kk][0]);
                float2 p2 = *(const float2*)(Ar + cx[kk][1]);
                float2 p3 = *(const float2*)(Ar + 1024 + cx[kk][1]);
                a[mi][0] = pack2(p0.x, p0.y);
                a[mi][1] = pack2(p1.x, p1.y);
                a[mi][2] = pack2(p2.x, p2.y);
                a[mi][3] = pack2(p3.x, p3.y);
            }
            #pragma unroll
            for (int nj = 0; nj < 4; nj++) {
                int j = wn*32 + nj*8 + g;
                uint32_t b[2] = { Bd[(kk*8 + tg)*104 + j], Bd[(kk*8 + tg + 4)*104 + j] };
                #pragma unroll
                for (int mi = 0; mi < 2; mi++) mma16(acc[mi][nj], a[mi], b);
            }
        }

        if (elect1()) MBAR_ARRIVE(hdr_s + 64 + st*8);
        if (warp == 0 && ks + 4 < 32) {
            MBAR_WAIT(hdr_s + 64 + st*8, ph);
            if (elect1()) issue_stage(ks + 4, st);
        }
    }

    const int b = bh >> 3, h = bh & 7;
    uint32_t* aop = (uint32_t*)g_aoh + ((size_t)(s*NBAT + b) * NTOK) * 384;
    #pragma unroll
    for (int mi = 0; mi < 2; mi++)
        #pragma unroll
        for (int nj = 0; nj < 4; nj++) {
            const int j = wn*32 + nj*8 + 2*tg;
            const int l = j >> 5, c = j & 31;
            #pragma unroll
            for (int half = 0; half < 2; half++) {
                const int row = mt*128 + wm*32 + mi*16 + g + half*8;
                uint32_t v = pack2(acc[mi][nj][half*2], acc[mi][nj][half*2+1]);
                aop[(size_t)row*384 + l*128 + h*16 + (c >> 1)] = v;
            }
        }
}

// =====================================================================
typedef CUresult (*tmap_encode_t)(
    CUtensorMap*, CUtensorMapDataType, cuuint32_t, void*,
    const cuuint64_t*, const cuuint64_t*, const cuuint32_t*, const cuuint32_t*,
    CUtensorMapInterleave, CUtensorMapSwizzle, CUtensorMapL2promotion,
    CUtensorMapFloatOOBfill);

extern "C" void kernel_launch(void* const* d_in, const int* in_sizes, int n_in,
                              void* d_out, int out_size)
{
    const float* att  = (const float*)d_in[0];
    const float* equ1 = (const float*)d_in[1];
    const float* equ2 = (const float*)d_in[2];
    const float* Wv   = (const float*)d_in[3];
    const float* Wo   = (const float*)d_in[4];
    float* out = (float*)d_out;

    tmap_encode_t enc = nullptr;
    cudaDriverEntryPointQueryResult qres;
    cudaGetDriverEntryPointByVersion("cuTensorMapEncodeTiled", (void**)&enc,
                                     12000, cudaEnableDefault, &qres);

    // attn A: 2D f32 (x=1024, y=131072), box (32,128), SW128
    static CUtensorMap tm_att;
    {
        cuuint64_t dims[2]    = { 1024, 2ull*64*1024 };
        cuuint64_t strides[1] = { NTOK * sizeof(float) };
        cuuint32_t box[2]     = { 32, 128 };
        cuuint32_t estr[2]    = { 1, 1 };
        enc(&tm_att, CU_TENSOR_MAP_DATA_TYPE_FLOAT32, 2, (void*)att,
            dims, strides, box, estr,
            CU_TENSOR_MAP_INTERLEAVE_NONE, CU_TENSOR_MAP_SWIZZLE_128B,
            CU_TENSOR_MAP_L2_PROMOTION_L2_128B, CU_TENSOR_MAP_FLOAT_OOB_FILL_NONE);
    }
    // equ 3D f32: (x=256, y=3, z=8192), box (32,1,128), SW128
    static CUtensorMap tm_e1, tm_e2;
    {
        cuuint64_t dims[3]    = { 256, 3, 8192 };
        cuuint64_t strides[2] = { 256*sizeof(float), 768*sizeof(float) };
        cuuint32_t box[3]     = { 32, 1, 128 };
        cuuint32_t estr[3]    = { 1, 1, 1 };
        enc(&tm_e1, CU_TENSOR_MAP_DATA_TYPE_FLOAT32, 3, (void*)equ1,
            dims, strides, box, estr,
            CU_TENSOR_MAP_INTERLEAVE_NONE, CU_TENSOR_MAP_SWIZZLE_128B,
            CU_TENSOR_MAP_L2_PROMOTION_L2_128B, CU_TENSOR_MAP_FLOAT_OOB_FILL_NONE);
        enc(&tm_e2, CU_TENSOR_MAP_DATA_TYPE_FLOAT32, 3, (void*)equ2,
            dims, strides, box, estr,
            CU_TENSOR_MAP_INTERLEAVE_NONE, CU_TENSOR_MAP_SWIZZLE_128B,
            CU_TENSOR_MAP_L2_PROMOTION_L2_128B, CU_TENSOR_MAP_FLOAT_OOB_FILL_NONE);
    }
    // aoh 2D fp16: (x=256, y=49152), box (64,128), SW128
    static CUtensorMap tm_ao;
    void* aoh_ptr = nullptr;
    cudaGetSymbolAddress(&aoh_ptr, g_aoh);
    {
        cuuint64_t dims[2]    = { 256, 2ull*RTOT };
        cuuint64_t strides[1] = { 256*sizeof(__half) };
        cuuint32_t box[2]     = { 64, 128 };
        cuuint32_t estr[2]    = { 1, 1 };
        enc(&tm_ao, CU_TENSOR_MAP_DATA_TYPE_BFLOAT16 /*same 2B; fp16 enum*/,
            2, aoh_ptr, dims, strides, box, estr,
            CU_TENSOR_MAP_INTERLEAVE_NONE, CU_TENSOR_MAP_SWIZZLE_128B,
            CU_TENSOR_MAP_L2_PROMOTION_L2_128B, CU_TENSOR_MAP_FLOAT_OOB_FILL_NONE);
    }
    // Wh 2D fp16: (x=256, y=512), box (64,64), SW128
    static CUtensorMap tm_w;
    void* wh_ptr = nullptr;
    cudaGetSymbolAddress(&wh_ptr, g_Wh);
    {
        cuuint64_t dims[2]    = { 256, 512 };
        cuuint64_t strides[1] = { 256*sizeof(__half) };
        cuuint32_t box[2]     = { 64, 64 };
        cuuint32_t estr[2]    = { 1, 1 };
        enc(&tm_w, CU_TENSOR_MAP_DATA_TYPE_BFLOAT16, 2, wh_ptr,
            dims, strides, box, estr,
            CU_TENSOR_MAP_INTERLEAVE_NONE, CU_TENSOR_MAP_SWIZZLE_128B,
            CU_TENSOR_MAP_L2_PROMOTION_L2_128B, CU_TENSOR_MAP_FLOAT_OOB_FILL_NONE);
    }

    const int P0S = 1024 + PW_OFF + 32768 + 4*16384;   // headroom + regions
    const int P1S = 1024 + PW_OFF + 32768 + 3*16384;
    cudaFuncSetAttribute(proj_kernel<0>, cudaFuncAttributeMaxDynamicSharedMemorySize, P0S);
    cudaFuncSetAttribute(proj_kernel<1>, cudaFuncAttributeMaxDynamicSharedMemorySize, P1S);
    cudaFuncSetAttribute(attn_kernel, cudaFuncAttributeMaxDynamicSharedMemorySize, ATTN_SMEM);

    wprep_kernel<<<CH*CH/256, 256>>>(Wv, Wo);
    proj_kernel<0><<<dim3(NTOK/128, 96, 2), 256, P0S>>>(tm_e1, tm_e2, tm_w, equ1, equ2, nullptr);
    attn_kernel<<<dim3(NTOK/128, NBAT*HEADS, 2), 384, ATTN_SMEM>>>(tm_att);
    proj_kernel<1><<<dim3(RTOT/128, CH/64, 2), 256, P1S>>>(tm_ao, tm_ao, tm_w, equ1, equ2, out);
}

// round 14
// speedup vs baseline: 1.0716x; 1.0716x over previous
#include <cuda.h>
#include <cuda_runtime.h>
#include <cuda_fp16.h>
#include <cstdint>

#define HEADS 8
#define NBAT  8
#define NTOK  1024
#define NL    3
#define CH    256
#define RTOT  (NBAT*NTOK*NL)   // 24576 rows per stream

// ---------------- scratch (device globals: allocation-free) ----------------
__device__ __align__(256) __half g_vph[2u*64u*512u*104u*2u];
__device__ __align__(256) __half g_aoh[2u*NBAT*NTOK*NL*CH];
__device__ __align__(256) __half g_Wh[2*CH*CH];

// ---------------- helpers ----------------
__device__ __forceinline__ void mma16(float* d, const uint32_t* a, const uint32_t* b) {
    asm("mma.sync.aligned.m16n8k16.row.col.f32.f16.f16.f32 "
        "{%0,%1,%2,%3}, {%4,%5,%6,%7}, {%8,%9}, {%0,%1,%2,%3};"
        : "+f"(d[0]), "+f"(d[1]), "+f"(d[2]), "+f"(d[3])
        : "r"(a[0]), "r"(a[1]), "r"(a[2]), "r"(a[3]), "r"(b[0]), "r"(b[1]));
}
__device__ __forceinline__ uint32_t pack2(float lo, float hi) {
    uint32_t r; asm("cvt.rn.f16x2.f32 %0, %1, %2;" : "=r"(r) : "f"(hi), "f"(lo)); return r;
}
__device__ __forceinline__ uint32_t elect1() {
    uint32_t p;
    asm volatile("{\n\t.reg .pred p;\n\telect.sync _|p, 0xFFFFFFFF;\n\t"
                 "selp.b32 %0, 1, 0, p;\n\t}" : "=r"(p));
    return p;
}
__device__ __forceinline__ void bulk_g2s(uint32_t dst, const void* src,
                                         uint32_t bytes, uint32_t mbar) {
    asm volatile("cp.async.bulk.shared::cta.global.mbarrier::complete_tx::bytes "
                 "[%0], [%1], %2, [%3];"
                 :: "r"(dst), "l"(src), "r"(bytes), "r"(mbar) : "memory");
}
__device__ __forceinline__ void tma2d(uint32_t dst, const CUtensorMap* tm,
                                      int x, int y, uint32_t mbar) {
    asm volatile(
        "cp.async.bulk.tensor.2d.shared::cta.global.tile.mbarrier::complete_tx::bytes "
        "[%0], [%1, {%2, %3}], [%4];"
        :: "r"(dst), "l"(tm), "r"(x), "r"(y), "r"(mbar) : "memory");
}
__device__ __forceinline__ void tma3d(uint32_t dst, const CUtensorMap* tm,
                                      int x, int y, int z, uint32_t mbar) {
    asm volatile(
        "cp.async.bulk.tensor.3d.shared::cta.global.tile.mbarrier::complete_tx::bytes "
        "[%0], [%1, {%2, %3, %4}], [%5];"
        :: "r"(dst), "l"(tm), "r"(x), "r"(y), "r"(z), "r"(mbar) : "memory");
}
#define MBAR_INIT(a, c) \
    asm volatile("mbarrier.init.shared.b64 [%0], %1;" :: "r"((uint32_t)(a)), "r"((uint32_t)(c)) : "memory")
#define MBAR_EXPECT(a, b) \
    asm volatile("mbarrier.arrive.expect_tx.shared.b64 _, [%0], %1;" :: "r"((uint32_t)(a)), "r"((uint32_t)(b)) : "memory")
#define MBAR_ARRIVE(a) \
    asm volatile("mbarrier.arrive.shared.b64 _, [%0];" :: "r"((uint32_t)(a)) : "memory")
#define MBAR_WAIT(mb, ph) do { \
    uint32_t _m = (uint32_t)(mb), _p = (uint32_t)(ph), _d; \
    asm volatile("{\n\t.reg .pred p;\n\t" \
        "mbarrier.try_wait.parity.acquire.cta.shared::cta.b64 p, [%1], %2;\n\t" \
        "selp.b32 %0, 1, 0, p;\n\t}" : "=r"(_d) : "r"(_m), "r"(_p) : "memory"); \
    if (!_d) { \
        asm volatile("{\n\t.reg .pred P1;\n\t" \
            "WL_%=:\n\t" \
            "mbarrier.try_wait.parity.acquire.cta.shared::cta.b64 P1, [%0], %1, 0x989680;\n\t" \
            "@P1 bra.uni WD_%=;\n\tbra.uni WL_%=;\n\tWD_%=:\n\t}" \
            :: "r"(_m), "r"(_p) : "memory"); \
    } \
} while(0)

// =====================================================================
__global__ void wprep_kernel(const float* __restrict__ Wv, const float* __restrict__ Wo) {
    int i = blockIdx.x * 256 + threadIdx.x;
    g_Wh[i]         = __float2half_rn(Wv[i]);
    g_Wh[CH*CH + i] = __float2half_rn(Wo[i]);
}

// =====================================================================
// proj (TMA + sync-free mbarrier pipeline, 8 warps 4x2, tile 128x64):
//  MODE 0: A=equ f32 via 3D TMA (rows (b,l,m)), 8 ksteps BK=32, 4 stages
//  MODE 1: A=g_aoh fp16 via 2D TMA, 4 ksteps BK=64, 3 stages
//  W: 64x256 fp16 tile preloaded once via 4 TMAs (own tx barrier).
//  s passed as param (stream-split launch), gridDim.z == 1.
// =====================================================================
#define PW_OFF  1024
#define PA_OFF  (1024 + 32768)

template<int MODE>
__global__ void __launch_bounds__(256, 2) proj_kernel(
    const __grid_constant__ CUtensorMap tA1,
    const __grid_constant__ CUtensorMap tA2,
    const __grid_constant__ CUtensorMap tW,
    const float* __restrict__ equ1, const float* __restrict__ equ2,
    float* __restrict__ out, const int s)
{
    constexpr int KS = (MODE == 0) ? 8 : 4;
    constexpr int ST = (MODE == 0) ? 4 : 3;
    constexpr int KKN = (MODE == 0) ? 2 : 4;

    extern __shared__ char psm[];
    char* hdr = (char*)(((uintptr_t)psm + 1023) & ~(uintptr_t)1023);
    const uint32_t hdr_s = (uint32_t)__cvta_generic_to_shared(hdr);
    char* Wp = hdr + PW_OFF;
    char* Ap = hdr + PA_OFF;
    const uint32_t W_s = hdr_s + PW_OFF;
    const uint32_t A_s = hdr_s + PA_OFF;

    const int tid = threadIdx.x;
    const int warp = tid >> 5, lane = tid & 31;
    const int wm = warp >> 1, wn = warp & 1;
    const int g = lane >> 2, tg = lane & 3;

    int mt = 0, bb = 0, ll = 0, jt = 0, rbase = 0, jbase;
    if constexpr (MODE == 0) {
        mt = blockIdx.x;
        int yy = blockIdx.y;
        jt = yy & 3; ll = (yy >> 2) % 3; bb = yy / 12;
        jbase = jt * 64;
    } else {
        rbase = blockIdx.x * 128;
        jbase = blockIdx.y * 64;
    }
    const int wy = (MODE ? 256 : 0) + jbase;

    if (tid == 0) {
        #pragma unroll
        for (int p = 0; p < ST; p++) {
            MBAR_INIT(hdr_s + p*8, 1);
            MBAR_INIT(hdr_s + 64 + p*8, 8);
        }
        MBAR_INIT(hdr_s + 128, 1);
    }
    __syncthreads();

    auto issue_stage = [&](int ks, int st) {
        MBAR_EXPECT(hdr_s + st*8, 16384);
        if constexpr (MODE == 0) {
            tma3d(A_s + st*16384, s ? &tA2 : &tA1,
                  ks*32, ll, bb*1024 + mt*128, hdr_s + st*8);
        } else {
            tma2d(A_s + st*16384, &tA1,
                  ks*64, s*RTOT + rbase, hdr_s + st*8);
        }
    };

    if (warp == 0 && elect1()) {
        MBAR_EXPECT(hdr_s + 128, 32768);
        #pragma unroll
        for (int q = 0; q < 4; q++)
            tma2d(W_s + q*8192, &tW, q*64, wy, hdr_s + 128);
        #pragma unroll
        for (int p = 0; p < ST; p++) issue_stage(p, p);
    }

    float acc[2][4][4];
    #pragma unroll
    for (int i = 0; i < 2; i++)
        #pragma unroll
        for (int j = 0; j < 4; j++)
            #pragma unroll
            for (int k = 0; k < 4; k++) acc[i][j][k] = 0.f;

    const uint32_t gx = (uint32_t)(g << 4);

    MBAR_WAIT(hdr_s + 128, 0);

    for (int ks = 0; ks < KS; ks++) {
        const int st = ks % ST;
        const int ph = (ks / ST) & 1;
        MBAR_WAIT(hdr_s + st*8, ph);

        const char* Ad = Ap + st * 16384;
        #pragma unroll
        for (int kk = 0; kk < KKN; kk++) {
            uint32_t a[2][4];
            #pragma unroll
            for (int mi = 0; mi < 2; mi++) {
                const int r = wm*32 + mi*16 + g;
                if constexpr (MODE == 0) {
                    const char* Ar = Ad + r * 128;
                    uint32_t c0 = (uint32_t)((kk*16 + 2*tg) * 4) ^ gx;
                    uint32_t c1 = (uint32_t)((kk*16 + 2*tg + 8) * 4) ^ gx;
                    float2 p0 = *(const float2*)(Ar + c0);
                    float2 p1 = *(const float2*)(Ar + 1024 + c0);
                    float2 p2 = *(const float2*)(Ar + c1);
                    float2 p3 = *(const float2*)(Ar + 1024 + c1);
                    a[mi][0] = pack2(p0.x, p0.y);
                    a[mi][1] = pack2(p1.x, p1.y);
                    a[mi][2] = pack2(p2.x, p2.y);
                    a[mi][3] = pack2(p3.x, p3.y);
                } else {
                    const char* Ar = Ad + r * 128;
                    uint32_t c0 = (uint32_t)((kk*8 + tg) * 4) ^ gx;
                    uint32_t c1 = (uint32_t)((kk*8 + tg + 4) * 4) ^ gx;
                    a[mi][0] = *(const uint32_t*)(Ar + c0);
                    a[mi][1] = *(const uint32_t*)(Ar + 1024 + c0);
                    a[mi][2] = *(const uint32_t*)(Ar + c1);
                    a[mi][3] = *(const uint32_t*)(Ar + 1024 + c1);
                }
            }
            const int q  = (MODE == 0) ? (ks >> 1) : ks;
            const int cb = (MODE == 0) ? ((ks & 1) * 16 + kk*8 + tg) : (kk*8 + tg);
            #pragma unroll
            for (int nj = 0; nj < 4; nj++) {
                const int j = wn*32 + nj*8 + g;
                const char* Wr = Wp + q*8192 + j*128;
                uint32_t b[2];
                b[0] = *(const uint32_t*)(Wr + (((uint32_t)(cb*4)) ^ gx));
                b[1] = *(const uint32_t*)(Wr + (((uint32_t)((cb+4)*4)) ^ gx));
                #pragma unroll
                for (int mi = 0; mi < 2; mi++) mma16(acc[mi][nj], a[mi], b);
            }
        }

        if (elect1()) MBAR_ARRIVE(hdr_s + 64 + st*8);
        if (warp == 0 && ks + ST < KS) {
            MBAR_WAIT(hdr_s + 64 + st*8, ph);
            if (elect1()) issue_stage(ks + ST, st);
        }
    }

    if constexpr (MODE == 0) {
        __syncthreads();
        __half* smh = (__half*)Wp;
        #pragma unroll
        for (int mi = 0; mi < 2; mi++)
            #pragma unroll
            for (int nj = 0; nj < 4; nj++) {
                const int jl = wn*32 + nj*8 + 2*tg;
                #pragma unroll
                for (int half = 0; half < 2; half++) {
                    const int ml = wm*32 + mi*16 + g + half*8;
                    smh[jl*138 + ml]     = __float2half_rn(acc[mi][nj][half*2]);
                    smh[(jl+1)*138 + ml] = __float2half_rn(acc[mi][nj][half*2+1]);
                }
            }
        __syncthreads();
        const uint32_t* smu = (const uint32_t*)Wp;
        uint32_t* vpu = (uint32_t*)g_vph;
        #pragma unroll
        for (int p = 0; p < 16; p++) {
            int idx = p*256 + tid;
            int j = idx & 63, mp = idx >> 6;
            uint32_t v = smu[j*69 + mp];
            int jg = jt*64 + j;
            int h = jg >> 5, c = jg & 31;
            int sbh = s*64 + bb*8 + h;
            vpu[((size_t)sbh*512 + mt*64 + mp)*104 + ll*32 + c] = v;
        }
    } else {
        #pragma unroll
        for (int mi = 0; mi < 2; mi++)
            #pragma unroll
            for (int nj = 0; nj < 4; nj++) {
                const int j = jbase + wn*32 + nj*8 + 2*tg;
                #pragma unroll
                for (int half = 0; half < 2; half++) {
                    const int r = rbase + wm*32 + mi*16 + g + half*8;
                    const float* R = s ? equ2 : equ1;
                    size_t o = (size_t)r*CH + j;
                    float2 rr = *(const float2*)&R[o];
                    float2 w = make_float2(acc[mi][nj][half*2] + rr.x,
                                           acc[mi][nj][half*2+1] + rr.y);
                    *(float2*)&out[(size_t)s*RTOT*CH + o] = w;
                }
            }
    }
}

// =====================================================================
// attn: unchanged from R10/R13 except s passed as param (stream split).
// =====================================================================
#define AT_STGB 23552
#define AT_BOFF 16384
#define AT_TX   23040
#define ATTN_SMEM (2048 + 4*AT_STGB)

__global__ void __launch_bounds__(384, 2) attn_kernel(
    const __grid_constant__ CUtensorMap tmap, const int s)
{
    extern __shared__ char smraw[];
    char* hdr = (char*)(((uintptr_t)smraw + 1023) & ~(uintptr_t)1023);
    char* datap = hdr + 1024;
    const uint32_t hdr_s = (uint32_t)__cvta_generic_to_shared(hdr);
    const uint32_t data_s = hdr_s + 1024;

    const int mt = blockIdx.x, bh = blockIdx.y;
    const int sbh = s*64 + bh;
    const int rowbase = sbh*1024 + mt*128;
    const uint32_t* vp = (const uint32_t*)g_vph + (size_t)sbh * 512 * 104;

    const int tid = threadIdx.x;
    const int warp = tid >> 5, lane = tid & 31;
    const int wm = warp & 3, wn = warp >> 2;
    const int g = lane >> 2, tg = lane & 3;

    if (tid == 0) {
        #pragma unroll
        for (int p = 0; p < 4; p++) {
            MBAR_INIT(hdr_s + p*8, 1);
            MBAR_INIT(hdr_s + 64 + p*8, 12);
        }
    }
    __syncthreads();

    auto issue_stage = [&](int ks, int st) {
        const uint32_t sofs = st * AT_STGB;
        MBAR_EXPECT(hdr_s + st*8, AT_TX);
        tma2d(data_s + sofs, &tmap, ks*32, rowbase, hdr_s + st*8);
        bulk_g2s(data_s + sofs + AT_BOFF, vp + (size_t)ks*16*104, 6656,
                 hdr_s + st*8);
    };

    if (warp == 0 && elect1()) {
        #pragma unroll
        for (int p = 0; p < 4; p++) issue_stage(p, p);
    }

    uint32_t cx[2][2];
    #pragma unroll
    for (int kk = 0; kk < 2; kk++)
        #pragma unroll
        for (int ss = 0; ss < 2; ss++)
            cx[kk][ss] = (uint32_t)((kk*64 + tg*8 + ss*32) ^ (g << 4));

    float acc[2][4][4];
    #pragma unroll
    for (int i = 0; i < 2; i++)
        #pragma unroll
        for (int j = 0; j < 4; j++)
            #pragma unroll
            for (int k = 0; k < 4; k++) acc[i][j][k] = 0.f;

    for (int ks = 0; ks < 32; ks++) {
        const int st = ks & 3;
        const int ph = (ks >> 2) & 1;
        MBAR_WAIT(hdr_s + st*8, ph);

        const char* Ad = datap + st * AT_STGB;
        const uint32_t* Bd = (const uint32_t*)(Ad + AT_BOFF);
        #pragma unroll
        for (int kk = 0; kk < 2; kk++) {
            uint32_t a[2][4];
            #pragma unroll
            for (int mi = 0; mi < 2; mi++) {
                const char* Ar = Ad + (wm*32 + mi*16 + g) * 128;
                float2 p0 = *(const float2*)(Ar + cx[kk][0]);
                float2 p1 = *(const float2*)(Ar + 1024 + cx[kk][0]);
                float2 p2 = *(const float2*)(Ar + cx[kk][1]);
                float2 p3 = *(const float2*)(Ar + 1024 + cx[kk][1]);
                a[mi][0] = pack2(p0.x, p0.y);
                a[mi][1] = pack2(p1.x, p1.y);
                a[mi][2] = pack2(p2.x, p2.y);
                a[mi][3] = pack2(p3.x, p3.y);
            }
            #pragma unroll
            for (int nj = 0; nj < 4; nj++) {
                int j = wn*32 + nj*8 + g;
                uint32_t b[2] = { Bd[(kk*8 + tg)*104 + j], Bd[(kk*8 + tg + 4)*104 + j] };
                #pragma unroll
                for (int mi = 0; mi < 2; mi++) mma16(acc[mi][nj], a[mi], b);
            }
        }

        if (elect1()) MBAR_ARRIVE(hdr_s + 64 + st*8);
        if (warp == 0 && ks + 4 < 32) {
            MBAR_WAIT(hdr_s + 64 + st*8, ph);
            if (elect1()) issue_stage(ks + 4, st);
        }
    }

    const int b = bh >> 3, h = bh & 7;
    uint32_t* aop = (uint32_t*)g_aoh + ((size_t)(s*NBAT + b) * NTOK) * 384;
    #pragma unroll
    for (int mi = 0; mi < 2; mi++)
        #pragma unroll
        for (int nj = 0; nj < 4; nj++) {
            const int j = wn*32 + nj*8 + 2*tg;
            const int l = j >> 5, c = j & 31;
            #pragma unroll
            for (int half = 0; half < 2; half++) {
                const int row = mt*128 + wm*32 + mi*16 + g + half*8;
                uint32_t v = pack2(acc[mi][nj][half*2], acc[mi][nj][half*2+1]);
                aop[(size_t)row*384 + l*128 + h*16 + (c >> 1)] = v;
            }
        }
}

// =====================================================================
typedef CUresult (*tmap_encode_t)(
    CUtensorMap*, CUtensorMapDataType, cuuint32_t, void*,
    const cuuint64_t*, const cuuint64_t*, const cuuint32_t*, const cuuint32_t*,
    CUtensorMapInterleave, CUtensorMapSwizzle, CUtensorMapL2promotion,
    CUtensorMapFloatOOBfill);

extern "C" void kernel_launch(void* const* d_in, const int* in_sizes, int n_in,
                              void* d_out, int out_size)
{
    const float* att  = (const float*)d_in[0];
    const float* equ1 = (const float*)d_in[1];
    const float* equ2 = (const float*)d_in[2];
    const float* Wv   = (const float*)d_in[3];
    const float* Wo   = (const float*)d_in[4];
    float* out = (float*)d_out;

    tmap_encode_t enc = nullptr;
    cudaDriverEntryPointQueryResult qres;
    cudaGetDriverEntryPointByVersion("cuTensorMapEncodeTiled", (void**)&enc,
                                     12000, cudaEnableDefault, &qres);

    static CUtensorMap tm_att;
    {
        cuuint64_t dims[2]    = { 1024, 2ull*64*1024 };
        cuuint64_t strides[1] = { NTOK * sizeof(float) };
        cuuint32_t box[2]     = { 32, 128 };
        cuuint32_t estr[2]    = { 1, 1 };
        enc(&tm_att, CU_TENSOR_MAP_DATA_TYPE_FLOAT32, 2, (void*)att,
            dims, strides, box, estr,
            CU_TENSOR_MAP_INTERLEAVE_NONE, CU_TENSOR_MAP_SWIZZLE_128B,
            CU_TENSOR_MAP_L2_PROMOTION_L2_128B, CU_TENSOR_MAP_FLOAT_OOB_FILL_NONE);
    }
    static CUtensorMap tm_e1, tm_e2;
    {
        cuuint64_t dims[3]    = { 256, 3, 8192 };
        cuuint64_t strides[2] = { 256*sizeof(float), 768*sizeof(float) };
        cuuint32_t box[3]     = { 32, 1, 128 };
        cuuint32_t estr[3]    = { 1, 1, 1 };
        enc(&tm_e1, CU_TENSOR_MAP_DATA_TYPE_FLOAT32, 3, (void*)equ1,
            dims, strides, box, estr,
            CU_TENSOR_MAP_INTERLEAVE_NONE, CU_TENSOR_MAP_SWIZZLE_128B,
            CU_TENSOR_MAP_L2_PROMOTION_L2_128B, CU_TENSOR_MAP_FLOAT_OOB_FILL_NONE);
        enc(&tm_e2, CU_TENSOR_MAP_DATA_TYPE_FLOAT32, 3, (void*)equ2,
            dims, strides, box, estr,
            CU_TENSOR_MAP_INTERLEAVE_NONE, CU_TENSOR_MAP_SWIZZLE_128B,
            CU_TENSOR_MAP_L2_PROMOTION_L2_128B, CU_TENSOR_MAP_FLOAT_OOB_FILL_NONE);
    }
    static CUtensorMap tm_ao;
    void* aoh_ptr = nullptr;
    cudaGetSymbolAddress(&aoh_ptr, g_aoh);
    {
        cuuint64_t dims[2]    = { 256, 2ull*RTOT };
        cuuint64_t strides[1] = { 256*sizeof(__half) };
        cuuint32_t box[2]     = { 64, 128 };
        cuuint32_t estr[2]    = { 1, 1 };
        enc(&tm_ao, CU_TENSOR_MAP_DATA_TYPE_BFLOAT16, 2, aoh_ptr,
            dims, strides, box, estr,
            CU_TENSOR_MAP_INTERLEAVE_NONE, CU_TENSOR_MAP_SWIZZLE_128B,
            CU_TENSOR_MAP_L2_PROMOTION_L2_128B, CU_TENSOR_MAP_FLOAT_OOB_FILL_NONE);
    }
    static CUtensorMap tm_w;
    void* wh_ptr = nullptr;
    cudaGetSymbolAddress(&wh_ptr, g_Wh);
    {
        cuuint64_t dims[2]    = { 256, 512 };
        cuuint64_t strides[1] = { 256*sizeof(__half) };
        cuuint32_t box[2]     = { 64, 64 };
        cuuint32_t estr[2]    = { 1, 1 };
        enc(&tm_w, CU_TENSOR_MAP_DATA_TYPE_BFLOAT16, 2, wh_ptr,
            dims, strides, box, estr,
            CU_TENSOR_MAP_INTERLEAVE_NONE, CU_TENSOR_MAP_SWIZZLE_128B,
            CU_TENSOR_MAP_L2_PROMOTION_L2_128B, CU_TENSOR_MAP_FLOAT_OOB_FILL_NONE);
    }

    const int P0S = 1024 + PW_OFF + 32768 + 4*16384;
    const int P1S = 1024 + PW_OFF + 32768 + 3*16384;
    cudaFuncSetAttribute(proj_kernel<0>, cudaFuncAttributeMaxDynamicSharedMemorySize, P0S);
    cudaFuncSetAttribute(proj_kernel<1>, cudaFuncAttributeMaxDynamicSharedMemorySize, P1S);
    cudaFuncSetAttribute(attn_kernel, cudaFuncAttributeMaxDynamicSharedMemorySize, ATTN_SMEM);

    // lazily-created side stream + fork/join events (capture-legal pattern)
    static cudaStream_t sB = nullptr;
    static cudaEvent_t ev_fork = nullptr, ev_join = nullptr;
    if (!sB) {
        cudaStreamCreateWithFlags(&sB, cudaStreamNonBlocking);
        cudaEventCreateWithFlags(&ev_fork, cudaEventDisableTiming);
        cudaEventCreateWithFlags(&ev_join, cudaEventDisableTiming);
    }

    // chain A (s=0) on the launch/capture stream; chain B (s=1) on sB.
    wprep_kernel<<<CH*CH/256, 256>>>(Wv, Wo);
    cudaEventRecord(ev_fork, 0);
    cudaStreamWaitEvent(sB, ev_fork, 0);

    proj_kernel<0><<<dim3(NTOK/128, 96, 1), 256, P0S>>>(
        tm_e1, tm_e2, tm_w, equ1, equ2, nullptr, 0);
    proj_kernel<0><<<dim3(NTOK/128, 96, 1), 256, P0S, sB>>>(
        tm_e1, tm_e2, tm_w, equ1, equ2, nullptr, 1);

    attn_kernel<<<dim3(NTOK/128, NBAT*HEADS, 1), 384, ATTN_SMEM>>>(tm_att, 0);
    attn_kernel<<<dim3(NTOK/128, NBAT*HEADS, 1), 384, ATTN_SMEM, sB>>>(tm_att, 1);

    proj_kernel<1><<<dim3(RTOT/128, 4, 1), 256, P1S>>>(
        tm_ao, tm_ao, tm_w, equ1, equ2, out, 0);
    proj_kernel<1><<<dim3(RTOT/128, 4, 1), 256, P1S, sB>>>(
        tm_ao, tm_ao, tm_w, equ1, equ2, out, 1);

    cudaEventRecord(ev_join, sB);
    cudaStreamWaitEvent(0, ev_join, 0);
}